// round 11
// baseline (speedup 1.0000x reference)
#include <cuda_runtime.h>

// GraphAggregation: out[b][d] = mean over 196 nodes of in[b][n*4 + d]
// in:  (B, 784) float32   out: (B, 4) float32
//
// HBM-streaming bound (416 MB, measured ceiling ~6.75-6.79 TB/s).
// This round: Blackwell 256-bit loads (ld.global.nc.v8.f32 -> LDG.E.256).
// Each warp owns 2 ADJACENT rows; each row = 98 aligned 32B chunks
// (3136 B row pitch, 32B-aligned). 6 full-warp 256-bit loads + merged
// 4-lane tail; same butterfly reduction epilogue as the locked R5 kernel.

struct __align__(32) f8 { float4 a, b; };

__device__ __forceinline__ f8 ldg256(const f8* p) {
    f8 r;
    asm volatile("ld.global.nc.v8.f32 {%0,%1,%2,%3,%4,%5,%6,%7}, [%8];"
                 : "=f"(r.a.x), "=f"(r.a.y), "=f"(r.a.z), "=f"(r.a.w),
                   "=f"(r.b.x), "=f"(r.b.y), "=f"(r.b.z), "=f"(r.b.w)
                 : "l"(p));
    return r;
}

__global__ void __launch_bounds__(256, 3)
graph_agg_kernel(const f8* __restrict__ in, float4* __restrict__ out, int B2)
{
    const int lane = threadIdx.x & 31;
    const int warp = (int)((blockIdx.x * (unsigned)blockDim.x + threadIdx.x) >> 5);
    if (warp >= B2) return;              // B2 = B/2 row-pairs

    const int r = warp * 2;
    const f8* rowA = in + (size_t)r * 98;    // 98 f8-chunks per row
    const f8* rowB = rowA + 98;

    // ---- front-batched independent 256-bit loads ----
    // Full-warp loads cover chunks [0,96) of each row.
    f8 va[3], vb[3];
    #pragma unroll
    for (int k = 0; k < 3; ++k) va[k] = ldg256(rowA + k * 32 + lane);
    #pragma unroll
    for (int k = 0; k < 3; ++k) vb[k] = ldg256(rowB + k * 32 + lane);

    // merged tail: lanes 0-1 load rowA chunks 96,97; lanes 2-3 rowB 96,97
    f8 t;
    t.a = make_float4(0.f, 0.f, 0.f, 0.f);
    t.b = make_float4(0.f, 0.f, 0.f, 0.f);
    if (lane < 4) {
        const f8* tp = (lane < 2) ? (rowA + 96 + lane) : (rowB + 94 + lane);
        t = ldg256(tp);
    }

    // ---- accumulate (each f8 = two node vectors) ----
    float ax = 0.f, ay = 0.f, az = 0.f, aw = 0.f;
    float bx = 0.f, by = 0.f, bz = 0.f, bw = 0.f;
    #pragma unroll
    for (int k = 0; k < 3; ++k) {
        ax += va[k].a.x + va[k].b.x;
        ay += va[k].a.y + va[k].b.y;
        az += va[k].a.z + va[k].b.z;
        aw += va[k].a.w + va[k].b.w;
        bx += vb[k].a.x + vb[k].b.x;
        by += vb[k].a.y + vb[k].b.y;
        bz += vb[k].a.z + vb[k].b.z;
        bw += vb[k].a.w + vb[k].b.w;
    }
    if (lane < 2) {
        ax += t.a.x + t.b.x; ay += t.a.y + t.b.y;
        az += t.a.z + t.b.z; aw += t.a.w + t.b.w;
    } else {
        bx += t.a.x + t.b.x; by += t.a.y + t.b.y;
        bz += t.a.z + t.b.z; bw += t.a.w + t.b.w;
    }

    // ---- butterfly reductions ----
    #pragma unroll
    for (int off = 16; off > 0; off >>= 1) {
        ax += __shfl_xor_sync(0xffffffffu, ax, off);
        ay += __shfl_xor_sync(0xffffffffu, ay, off);
        az += __shfl_xor_sync(0xffffffffu, az, off);
        aw += __shfl_xor_sync(0xffffffffu, aw, off);
        bx += __shfl_xor_sync(0xffffffffu, bx, off);
        by += __shfl_xor_sync(0xffffffffu, by, off);
        bz += __shfl_xor_sync(0xffffffffu, bz, off);
        bw += __shfl_xor_sync(0xffffffffu, bw, off);
    }

    if (lane == 0) {
        const float s = 1.0f / 196.0f;
        out[r]     = make_float4(ax * s, ay * s, az * s, aw * s);
        out[r + 1] = make_float4(bx * s, by * s, bz * s, bw * s);
    }
}

extern "C" void kernel_launch(void* const* d_in, const int* in_sizes, int n_in,
                              void* d_out, int out_size)
{
    const f8* in      = (const f8*)d_in[0];
    float4*   out     = (float4*)d_out;
    const int B  = in_sizes[0] / 784;         // 131072 (even)
    const int B2 = B / 2;                     // row-pairs

    const int threads = 256;                  // 8 warps/block -> 16 rows/block
    const int blocks  = (B2 + 7) / 8;         // 8192

    graph_agg_kernel<<<blocks, threads>>>(in, out, B2);
}